// round 13
// baseline (speedup 1.0000x reference)
#include <cuda_runtime.h>
#include <math.h>

#define MU_ELEMS (32*100*64)      // 204800
#define SG_ELEMS (32*100*100*64)  // 20480000

typedef unsigned long long u64;

__device__ __forceinline__ void ffma2(u64& d, u64 a, u64 b) {
    asm("fma.rn.f32x2 %0, %1, %2, %0;" : "+l"(d) : "l"(a), "l"(b));
}
__device__ __forceinline__ u64 pack2(float lo, float hi) {
    u64 r; asm("mov.b64 %0, {%1, %2};" : "=l"(r) : "f"(lo), "f"(hi)); return r;
}
__device__ __forceinline__ float unpack_sum(u64 v) {
    float lo, hi; asm("mov.b64 {%0, %1}, %2;" : "=f"(lo), "=f"(hi) : "l"(v));
    return lo + hi;
}

// 640 blocks = 32 b x 20 p-strips (5 p each), 256 threads (8 warps):
//  w0-3: Gram strip G[5p][100q]: qhalf = w&1 (64 q), kkhalf = w>>1;
//        even/odd-c partials packed in u64 via fma.rn.f32x2.
//        w0/w1 -> sGp[0], w2/w3 -> sGp[1] (disjoint q), merged after barrier.
//  w4-5: conv (mu_out), kk-split 2-way, k=lane/lane+32, 5 ox, packed c
//  w6-7: diag_vals, same layout over Sigma-diag window, packed c
__global__ __launch_bounds__(256) void fused_kernel(
    const float* __restrict__ mu_in, const float* __restrict__ Sigma_in,
    const float* __restrict__ w_mu, const float* __restrict__ w_sigma,
    float* __restrict__ mu_out, float* __restrict__ sigma_out)
{
    __shared__ __align__(16) float smu[196 * 36];  // 28224 B: mu_in[b], n-major, pad 36
    __shared__ __align__(16) float sds[2240];      //  8960 B: Sigma diag window 5x14x32
    __shared__ __align__(16) float sGp[2][500];    //  4000 B: Gram partials [kkhalf][pl*100+q]
    __shared__ __align__(16) float pcv[2][320];    //  2560 B: conv partials [kg][pl*64+k]
    __shared__ __align__(16) float pdi[2][320];    //  2560 B: diag partials
    __shared__ __align__(16) float ssp[64];        //   256 B  (total 46560 < 49152)

    const int bid = blockIdx.x;
    const int b   = bid / 20;
    const int pt  = bid % 20;
    const int oy  = pt >> 1;
    const int oxb = (pt & 1) * 5;
    const int tid = threadIdx.x;
    const int w    = tid >> 5;
    const int lane = tid & 31;

    for (int i = tid; i < 6272; i += 256) {
        int n = i >> 5, c = i & 31;
        smu[n * 36 + c] = mu_in[(size_t)(b * 196 + n) * 32 + c];
    }
    for (int i = tid; i < 2240; i += 256) {
        int r = i / 448, rem = i - r * 448;
        int x = rem >> 5, c = rem & 31;
        int n = (oy + r) * 14 + x;
        sds[i] = Sigma_in[(((size_t)b * 196 + n) * 196 + n) * 32 + c];
    }
    if (tid < 64) ssp[tid] = log1pf(expf(w_sigma[tid]));
    __syncthreads();

    if (w < 4) {
        // ---------------- GRAM (packed-c FFMA2) ----------------
        const int qh  = w & 1;
        const int kg  = w >> 1;
        const int kk0 = kg ? 13 : 0;
        const int kk1 = kg ? 25 : 13;
        int q[2], nq[2];
        #pragma unroll
        for (int j = 0; j < 2; j++) {
            q[j] = qh * 64 + j * 32 + lane;
            int qc = (q[j] < 100) ? q[j] : 0;
            nq[j] = (qc / 10) * 14 + qc % 10;
        }
        u64 gacc2[2][5];
        #pragma unroll
        for (int j = 0; j < 2; j++)
            #pragma unroll
            for (int pl = 0; pl < 5; pl++) gacc2[j][pl] = 0ull;

        const int prow0 = oy * 14 + oxb;
        #pragma unroll 1
        for (int kk = kk0; kk < kk1; kk++) {
            const int off = (kk / 5) * 14 + (kk % 5);
            const ulonglong2* b0 = (const ulonglong2*)(smu + (nq[0] + off) * 36);
            const ulonglong2* b1 = (const ulonglong2*)(smu + (nq[1] + off) * 36);
            const float* ar = smu + (prow0 + off) * 36;
            #pragma unroll
            for (int c4 = 0; c4 < 8; c4++) {
                ulonglong2 q0 = b0[c4];
                ulonglong2 q1 = b1[c4];
                #pragma unroll
                for (int pl = 0; pl < 5; pl++) {
                    ulonglong2 av = *(const ulonglong2*)(ar + pl * 36 + c4 * 4); // broadcast
                    ffma2(gacc2[0][pl], av.x, q0.x);
                    ffma2(gacc2[0][pl], av.y, q0.y);
                    ffma2(gacc2[1][pl], av.x, q1.x);
                    ffma2(gacc2[1][pl], av.y, q1.y);
                }
            }
        }
        #pragma unroll
        for (int j = 0; j < 2; j++) {
            if (q[j] < 100) {
                #pragma unroll
                for (int pl = 0; pl < 5; pl++)
                    sGp[kg][pl * 100 + q[j]] = unpack_sum(gacc2[j][pl]);
            }
        }
    } else if (w < 6) {
        // ---------------- CONV (packed-c FFMA2) ----------------
        const int kg  = w - 4;
        const int kk0 = kg ? 13 : 0;
        const int kk1 = kg ? 25 : 13;
        const float* wk = w_mu + lane;
        u64 acc2[10];
        #pragma unroll
        for (int j = 0; j < 10; j++) acc2[j] = 0ull;

        #pragma unroll 1
        for (int kk = kk0; kk < kk1; kk++) {
            const int off = (kk / 5) * 14 + (kk % 5);
            const float* mrow = smu + (oy * 14 + oxb + off) * 36;
            #pragma unroll
            for (int c4 = 0; c4 < 8; c4++) {
                const int m = kk * 32 + c4 * 4;
                float wa0 = wk[(m + 0) * 64], wb0 = wk[(m + 0) * 64 + 32];
                float wa1 = wk[(m + 1) * 64], wb1 = wk[(m + 1) * 64 + 32];
                float wa2 = wk[(m + 2) * 64], wb2 = wk[(m + 2) * 64 + 32];
                float wa3 = wk[(m + 3) * 64], wb3 = wk[(m + 3) * 64 + 32];
                u64 wA01 = pack2(wa0, wa1), wA23 = pack2(wa2, wa3);
                u64 wB01 = pack2(wb0, wb1), wB23 = pack2(wb2, wb3);
                #pragma unroll
                for (int j = 0; j < 5; j++) {
                    ulonglong2 mv = *(const ulonglong2*)(mrow + j * 36 + c4 * 4);
                    ffma2(acc2[j],     mv.x, wA01);
                    ffma2(acc2[j],     mv.y, wA23);
                    ffma2(acc2[5 + j], mv.x, wB01);
                    ffma2(acc2[5 + j], mv.y, wB23);
                }
            }
        }
        #pragma unroll
        for (int j = 0; j < 5; j++) {
            pcv[kg][j * 64 + lane]      = unpack_sum(acc2[j]);
            pcv[kg][j * 64 + 32 + lane] = unpack_sum(acc2[5 + j]);
        }
    } else {
        // ---------------- DIAG (packed-c FFMA2) ----------------
        const int kg  = w - 6;
        const int kk0 = kg ? 13 : 0;
        const int kk1 = kg ? 25 : 13;
        const float* wk = w_mu + lane;
        const u64 sp2a = pack2(ssp[lane], ssp[lane]);
        const u64 sp2b = pack2(ssp[lane + 32], ssp[lane + 32]);
        u64 acc2[10];
        #pragma unroll
        for (int j = 0; j < 10; j++) acc2[j] = 0ull;

        #pragma unroll 1
        for (int kk = kk0; kk < kk1; kk++) {
            const float* drow = sds + ((kk / 5) * 14 + (kk % 5) + oxb) * 32;
            #pragma unroll
            for (int c4 = 0; c4 < 8; c4++) {
                const int m = kk * 32 + c4 * 4;
                float wa0 = wk[(m + 0) * 64], wb0 = wk[(m + 0) * 64 + 32];
                float wa1 = wk[(m + 1) * 64], wb1 = wk[(m + 1) * 64 + 32];
                float wa2 = wk[(m + 2) * 64], wb2 = wk[(m + 2) * 64 + 32];
                float wa3 = wk[(m + 3) * 64], wb3 = wk[(m + 3) * 64 + 32];
                u64 wA01 = pack2(wa0, wa1), wA23 = pack2(wa2, wa3);
                u64 wB01 = pack2(wb0, wb1), wB23 = pack2(wb2, wb3);
                u64 eA01 = sp2a; ffma2(eA01, wA01, wA01);
                u64 eA23 = sp2a; ffma2(eA23, wA23, wA23);
                u64 eB01 = sp2b; ffma2(eB01, wB01, wB01);
                u64 eB23 = sp2b; ffma2(eB23, wB23, wB23);
                #pragma unroll
                for (int j = 0; j < 5; j++) {
                    ulonglong2 dv = *(const ulonglong2*)(drow + j * 32 + c4 * 4);
                    ffma2(acc2[j],     dv.x, eA01);
                    ffma2(acc2[j],     dv.y, eA23);
                    ffma2(acc2[5 + j], dv.x, eB01);
                    ffma2(acc2[5 + j], dv.y, eB23);
                }
            }
        }
        #pragma unroll
        for (int j = 0; j < 5; j++) {
            pdi[kg][j * 64 + lane]      = unpack_sum(acc2[j]);
            pdi[kg][j * 64 + 32 + lane] = unpack_sum(acc2[5 + j]);
        }
    }
    __syncthreads();

    // merge Gram kk-halves; write mu_out
    for (int i = tid; i < 500; i += 256)
        sGp[0][i] += sGp[1][i];
    if (mu_out != nullptr) {
        for (int i = tid; i < 320; i += 256) {
            int pl = i >> 6, k = i & 63;
            mu_out[(b * 100 + pt * 5 + pl) * 64 + k] = pcv[0][i] + pcv[1][i];
        }
    }
    __syncthreads();

    if (sigma_out == nullptr) return;

    // patch diagonal entries (q == p): add diag_vals, then abs where q==k
    for (int i = tid; i < 320; i += 256) {
        int pl = i >> 6, k = i & 63;
        int pg = pt * 5 + pl;
        float val = ssp[k] * sGp[0][pl * 100 + pg] + pdi[0][i] + pdi[1][i];
        if (pg == k) val = fabsf(val);
        sigma_out[(((size_t)(b * 100 + pg)) * 100 + pg) * 64 + k] = val;
    }

    // writer: all (p in strip, q != p, k): sp[k]*G, abs at q==k
    // kq = tid & 15 is invariant under +=256 -> hoist s4, k0.
    {
        const float4* sp4 = (const float4*)ssp;
        float4* out4 = (float4*)sigma_out;
        const int kq = tid & 15;
        const float4 s4 = sp4[kq];
        const int k0 = kq * 4;
        for (int t = tid >> 4; t < 500; t += 16) {
            const int pl = t / 100, ql = t - pl * 100;
            const int pg = pt * 5 + pl;
            if (ql == pg) continue;             // diagonal handled by patch
            const float g = sGp[0][pl * 100 + ql];
            float4 v;
            v.x = s4.x * g; v.y = s4.y * g; v.z = s4.z * g; v.w = s4.w * g;
            if      (ql == k0    ) v.x = fabsf(v.x);
            else if (ql == k0 + 1) v.y = fabsf(v.y);
            else if (ql == k0 + 2) v.z = fabsf(v.z);
            else if (ql == k0 + 3) v.w = fabsf(v.w);
            out4[((size_t)(b * 100 + pg) * 100 + ql) * 16 + kq] = v;
        }
    }
}

extern "C" void kernel_launch(void* const* d_in, const int* in_sizes, int n_in,
                              void* d_out, int out_size)
{
    const float* mu_in    = (const float*)d_in[0];
    const float* Sigma_in = (const float*)d_in[1];
    const float* w_mu     = (const float*)d_in[2];
    const float* w_sigma  = (const float*)d_in[3];
    for (int i = 0; i < n_in && i < 8; i++) {
        switch (in_sizes[i]) {
            case 32*14*14*32:  mu_in    = (const float*)d_in[i]; break;
            case 39337984:     Sigma_in = (const float*)d_in[i]; break;
            case 5*5*32*64:    w_mu     = (const float*)d_in[i]; break;
            case 64:           w_sigma  = (const float*)d_in[i]; break;
            default: break;
        }
    }

    float* out = (float*)d_out;
    float* mu_ptr  = nullptr;
    float* sig_ptr = nullptr;
    if (out_size == MU_ELEMS + SG_ELEMS) { mu_ptr = out; sig_ptr = out + MU_ELEMS; }
    else if (out_size == SG_ELEMS)       { sig_ptr = out; }
    else if (out_size == MU_ELEMS)       { mu_ptr = out; }
    else                                 { mu_ptr = out; sig_ptr = out + MU_ELEMS; }

    fused_kernel<<<640, 256>>>(mu_in, Sigma_in, w_mu, w_sigma, mu_ptr, sig_ptr);
}

// round 14
// speedup vs baseline: 1.0082x; 1.0082x over previous
#include <cuda_runtime.h>
#include <math.h>

#define MU_ELEMS (32*100*64)      // 204800
#define SG_ELEMS (32*100*100*64)  // 20480000

typedef unsigned long long u64;

__device__ __forceinline__ void ffma2(u64& d, u64 a, u64 b) {
    asm("fma.rn.f32x2 %0, %1, %2, %0;" : "+l"(d) : "l"(a), "l"(b));
}
__device__ __forceinline__ u64 pack2(float lo, float hi) {
    u64 r; asm("mov.b64 %0, {%1, %2};" : "=l"(r) : "f"(lo), "f"(hi)); return r;
}
__device__ __forceinline__ float unpack_sum(u64 v) {
    float lo, hi; asm("mov.b64 {%0, %1}, %2;" : "=f"(lo), "=f"(hi) : "l"(v));
    return lo + hi;
}

// 640 blocks = 32 b x 20 p-strips (5 p each), 256 threads (8 warps):
//  w0-3: Gram strip G[5p][100q]: qhalf = w&1 (64 q), kkhalf = w>>1;
//        even/odd-c partials packed in u64 via fma.rn.f32x2.
//        w0/w1 -> sGp[0], w2/w3 -> sGp[1] (disjoint q), merged after barrier.
//  w4-5: conv (mu_out), kk-split 2-way, k=lane/lane+32, 5 ox, packed c
//  w6-7: diag_vals, same layout over Sigma-diag window, packed c
__global__ __launch_bounds__(256) void fused_kernel(
    const float* __restrict__ mu_in, const float* __restrict__ Sigma_in,
    const float* __restrict__ w_mu, const float* __restrict__ w_sigma,
    float* __restrict__ mu_out, float* __restrict__ sigma_out)
{
    __shared__ __align__(16) float smu[196 * 36];  // 28224 B: mu_in[b], n-major, pad 36
    __shared__ __align__(16) float sds[2240];      //  8960 B: Sigma diag window 5x14x32
    __shared__ __align__(16) float sGp[2][500];    //  4000 B: Gram partials [kkhalf][pl*100+q]
    __shared__ __align__(16) float pcv[2][320];    //  2560 B: conv partials [kg][pl*64+k]
    __shared__ __align__(16) float pdi[2][320];    //  2560 B: diag partials
    __shared__ __align__(16) float ssp[64];        //   256 B  (total 46560 < 49152)

    const int bid = blockIdx.x;
    const int b   = bid / 20;
    const int pt  = bid % 20;
    const int oy  = pt >> 1;
    const int oxb = (pt & 1) * 5;
    const int tid = threadIdx.x;
    const int w    = tid >> 5;
    const int lane = tid & 31;

    for (int i = tid; i < 6272; i += 256) {
        int n = i >> 5, c = i & 31;
        smu[n * 36 + c] = mu_in[(size_t)(b * 196 + n) * 32 + c];
    }
    for (int i = tid; i < 2240; i += 256) {
        int r = i / 448, rem = i - r * 448;
        int x = rem >> 5, c = rem & 31;
        int n = (oy + r) * 14 + x;
        sds[i] = Sigma_in[(((size_t)b * 196 + n) * 196 + n) * 32 + c];
    }
    if (tid < 64) ssp[tid] = log1pf(expf(w_sigma[tid]));
    __syncthreads();

    if (w < 4) {
        // ---------------- GRAM (packed-c FFMA2) ----------------
        const int qh  = w & 1;
        const int kg  = w >> 1;
        const int kk0 = kg ? 13 : 0;
        const int kk1 = kg ? 25 : 13;
        int q[2], nq[2];
        #pragma unroll
        for (int j = 0; j < 2; j++) {
            q[j] = qh * 64 + j * 32 + lane;
            int qc = (q[j] < 100) ? q[j] : 0;
            nq[j] = (qc / 10) * 14 + qc % 10;
        }
        u64 gacc2[2][5];
        #pragma unroll
        for (int j = 0; j < 2; j++)
            #pragma unroll
            for (int pl = 0; pl < 5; pl++) gacc2[j][pl] = 0ull;

        const int prow0 = oy * 14 + oxb;
        #pragma unroll 1
        for (int kk = kk0; kk < kk1; kk++) {
            const int off = (kk / 5) * 14 + (kk % 5);
            const ulonglong2* b0 = (const ulonglong2*)(smu + (nq[0] + off) * 36);
            const ulonglong2* b1 = (const ulonglong2*)(smu + (nq[1] + off) * 36);
            const float* ar = smu + (prow0 + off) * 36;
            #pragma unroll
            for (int c4 = 0; c4 < 8; c4++) {
                ulonglong2 q0 = b0[c4];
                ulonglong2 q1 = b1[c4];
                #pragma unroll
                for (int pl = 0; pl < 5; pl++) {
                    ulonglong2 av = *(const ulonglong2*)(ar + pl * 36 + c4 * 4); // broadcast
                    ffma2(gacc2[0][pl], av.x, q0.x);
                    ffma2(gacc2[0][pl], av.y, q0.y);
                    ffma2(gacc2[1][pl], av.x, q1.x);
                    ffma2(gacc2[1][pl], av.y, q1.y);
                }
            }
        }
        #pragma unroll
        for (int j = 0; j < 2; j++) {
            if (q[j] < 100) {
                #pragma unroll
                for (int pl = 0; pl < 5; pl++)
                    sGp[kg][pl * 100 + q[j]] = unpack_sum(gacc2[j][pl]);
            }
        }
    } else if (w < 6) {
        // ---------------- CONV (packed-c FFMA2) ----------------
        const int kg  = w - 4;
        const int kk0 = kg ? 13 : 0;
        const int kk1 = kg ? 25 : 13;
        const float* wk = w_mu + lane;
        u64 acc2[10];
        #pragma unroll
        for (int j = 0; j < 10; j++) acc2[j] = 0ull;

        #pragma unroll 1
        for (int kk = kk0; kk < kk1; kk++) {
            const int off = (kk / 5) * 14 + (kk % 5);
            const float* mrow = smu + (oy * 14 + oxb + off) * 36;
            #pragma unroll
            for (int c4 = 0; c4 < 8; c4++) {
                const int m = kk * 32 + c4 * 4;
                float wa0 = wk[(m + 0) * 64], wb0 = wk[(m + 0) * 64 + 32];
                float wa1 = wk[(m + 1) * 64], wb1 = wk[(m + 1) * 64 + 32];
                float wa2 = wk[(m + 2) * 64], wb2 = wk[(m + 2) * 64 + 32];
                float wa3 = wk[(m + 3) * 64], wb3 = wk[(m + 3) * 64 + 32];
                u64 wA01 = pack2(wa0, wa1), wA23 = pack2(wa2, wa3);
                u64 wB01 = pack2(wb0, wb1), wB23 = pack2(wb2, wb3);
                #pragma unroll
                for (int j = 0; j < 5; j++) {
                    ulonglong2 mv = *(const ulonglong2*)(mrow + j * 36 + c4 * 4);
                    ffma2(acc2[j],     mv.x, wA01);
                    ffma2(acc2[j],     mv.y, wA23);
                    ffma2(acc2[5 + j], mv.x, wB01);
                    ffma2(acc2[5 + j], mv.y, wB23);
                }
            }
        }
        #pragma unroll
        for (int j = 0; j < 5; j++) {
            pcv[kg][j * 64 + lane]      = unpack_sum(acc2[j]);
            pcv[kg][j * 64 + 32 + lane] = unpack_sum(acc2[5 + j]);
        }
    } else {
        // ---------------- DIAG (packed-c FFMA2) ----------------
        const int kg  = w - 6;
        const int kk0 = kg ? 13 : 0;
        const int kk1 = kg ? 25 : 13;
        const float* wk = w_mu + lane;
        const u64 sp2a = pack2(ssp[lane], ssp[lane]);
        const u64 sp2b = pack2(ssp[lane + 32], ssp[lane + 32]);
        u64 acc2[10];
        #pragma unroll
        for (int j = 0; j < 10; j++) acc2[j] = 0ull;

        #pragma unroll 1
        for (int kk = kk0; kk < kk1; kk++) {
            const float* drow = sds + ((kk / 5) * 14 + (kk % 5) + oxb) * 32;
            #pragma unroll
            for (int c4 = 0; c4 < 8; c4++) {
                const int m = kk * 32 + c4 * 4;
                float wa0 = wk[(m + 0) * 64], wb0 = wk[(m + 0) * 64 + 32];
                float wa1 = wk[(m + 1) * 64], wb1 = wk[(m + 1) * 64 + 32];
                float wa2 = wk[(m + 2) * 64], wb2 = wk[(m + 2) * 64 + 32];
                float wa3 = wk[(m + 3) * 64], wb3 = wk[(m + 3) * 64 + 32];
                u64 wA01 = pack2(wa0, wa1), wA23 = pack2(wa2, wa3);
                u64 wB01 = pack2(wb0, wb1), wB23 = pack2(wb2, wb3);
                u64 eA01 = sp2a; ffma2(eA01, wA01, wA01);
                u64 eA23 = sp2a; ffma2(eA23, wA23, wA23);
                u64 eB01 = sp2b; ffma2(eB01, wB01, wB01);
                u64 eB23 = sp2b; ffma2(eB23, wB23, wB23);
                #pragma unroll
                for (int j = 0; j < 5; j++) {
                    ulonglong2 dv = *(const ulonglong2*)(drow + j * 32 + c4 * 4);
                    ffma2(acc2[j],     dv.x, eA01);
                    ffma2(acc2[j],     dv.y, eA23);
                    ffma2(acc2[5 + j], dv.x, eB01);
                    ffma2(acc2[5 + j], dv.y, eB23);
                }
            }
        }
        #pragma unroll
        for (int j = 0; j < 5; j++) {
            pdi[kg][j * 64 + lane]      = unpack_sum(acc2[j]);
            pdi[kg][j * 64 + 32 + lane] = unpack_sum(acc2[5 + j]);
        }
    }
    __syncthreads();

    // merge Gram kk-halves; write mu_out
    for (int i = tid; i < 500; i += 256)
        sGp[0][i] += sGp[1][i];
    if (mu_out != nullptr) {
        for (int i = tid; i < 320; i += 256) {
            int pl = i >> 6, k = i & 63;
            mu_out[(b * 100 + pt * 5 + pl) * 64 + k] = pcv[0][i] + pcv[1][i];
        }
    }
    __syncthreads();

    if (sigma_out == nullptr) return;

    // patch diagonal entries (q == p): add diag_vals, then abs where q==k
    for (int i = tid; i < 320; i += 256) {
        int pl = i >> 6, k = i & 63;
        int pg = pt * 5 + pl;
        float val = ssp[k] * sGp[0][pl * 100 + pg] + pdi[0][i] + pdi[1][i];
        if (pg == k) val = fabsf(val);
        sigma_out[(((size_t)(b * 100 + pg)) * 100 + pg) * 64 + k] = val;
    }

    // writer: all (p in strip, q != p, k): sp[k]*G, abs at q==k
    // kq = tid & 15 is invariant under +=256 -> hoist s4, k0.
    {
        const float4* sp4 = (const float4*)ssp;
        float4* out4 = (float4*)sigma_out;
        const int kq = tid & 15;
        const float4 s4 = sp4[kq];
        const int k0 = kq * 4;
        for (int t = tid >> 4; t < 500; t += 16) {
            const int pl = t / 100, ql = t - pl * 100;
            const int pg = pt * 5 + pl;
            if (ql == pg) continue;             // diagonal handled by patch
            const float g = sGp[0][pl * 100 + ql];
            float4 v;
            v.x = s4.x * g; v.y = s4.y * g; v.z = s4.z * g; v.w = s4.w * g;
            if      (ql == k0    ) v.x = fabsf(v.x);
            else if (ql == k0 + 1) v.y = fabsf(v.y);
            else if (ql == k0 + 2) v.z = fabsf(v.z);
            else if (ql == k0 + 3) v.w = fabsf(v.w);
            out4[((size_t)(b * 100 + pg) * 100 + ql) * 16 + kq] = v;
        }
    }
}

extern "C" void kernel_launch(void* const* d_in, const int* in_sizes, int n_in,
                              void* d_out, int out_size)
{
    const float* mu_in    = (const float*)d_in[0];
    const float* Sigma_in = (const float*)d_in[1];
    const float* w_mu     = (const float*)d_in[2];
    const float* w_sigma  = (const float*)d_in[3];
    for (int i = 0; i < n_in && i < 8; i++) {
        switch (in_sizes[i]) {
            case 32*14*14*32:  mu_in    = (const float*)d_in[i]; break;
            case 39337984:     Sigma_in = (const float*)d_in[i]; break;
            case 5*5*32*64:    w_mu     = (const float*)d_in[i]; break;
            case 64:           w_sigma  = (const float*)d_in[i]; break;
            default: break;
        }
    }

    float* out = (float*)d_out;
    float* mu_ptr  = nullptr;
    float* sig_ptr = nullptr;
    if (out_size == MU_ELEMS + SG_ELEMS) { mu_ptr = out; sig_ptr = out + MU_ELEMS; }
    else if (out_size == SG_ELEMS)       { sig_ptr = out; }
    else if (out_size == MU_ELEMS)       { mu_ptr = out; }
    else                                 { mu_ptr = out; sig_ptr = out + MU_ELEMS; }

    fused_kernel<<<640, 256>>>(mu_in, Sigma_in, w_mu, w_sigma, mu_ptr, sig_ptr);
}

// round 15
// speedup vs baseline: 1.0134x; 1.0052x over previous
#include <cuda_runtime.h>
#include <math.h>

#define MU_ELEMS (32*100*64)      // 204800
#define SG_ELEMS (32*100*100*64)  // 20480000

typedef unsigned long long u64;

__device__ __forceinline__ void ffma2(u64& d, u64 a, u64 b) {
    asm("fma.rn.f32x2 %0, %1, %2, %0;" : "+l"(d) : "l"(a), "l"(b));
}
__device__ __forceinline__ u64 pack2(float lo, float hi) {
    u64 r; asm("mov.b64 %0, {%1, %2};" : "=l"(r) : "f"(lo), "f"(hi)); return r;
}
__device__ __forceinline__ float unpack_sum(u64 v) {
    float lo, hi; asm("mov.b64 {%0, %1}, %2;" : "=f"(lo), "=f"(hi) : "l"(v));
    return lo + hi;
}

// 640 blocks = 32 b x 20 p-strips (5 p each), 256 threads (8 warps):
//  w0-3: Gram strip G[5p][100q]: qhalf = w&1 (64 q), kkhalf = w>>1;
//        even/odd-c partials packed in u64 via fma.rn.f32x2.
//        w0/w1 -> sGp[0], w2/w3 -> sGp[1] (disjoint q), merged after barrier.
//  w4-5: conv (mu_out), kk-split 2-way, k=lane/lane+32, 5 ox, packed c
//  w6-7: diag_vals, same layout over Sigma-diag window, packed c
__global__ __launch_bounds__(256) void fused_kernel(
    const float* __restrict__ mu_in, const float* __restrict__ Sigma_in,
    const float* __restrict__ w_mu, const float* __restrict__ w_sigma,
    float* __restrict__ mu_out, float* __restrict__ sigma_out)
{
    __shared__ __align__(16) float smu[196 * 36];  // 28224 B: mu_in[b], n-major, pad 36
    __shared__ __align__(16) float sds[2240];      //  8960 B: Sigma diag window 5x14x32
    __shared__ __align__(16) float sGp[2][500];    //  4000 B: Gram partials [kkhalf][pl*100+q]
    __shared__ __align__(16) float pcv[2][320];    //  2560 B: conv partials [kg][pl*64+k]
    __shared__ __align__(16) float pdi[2][320];    //  2560 B: diag partials
    __shared__ __align__(16) float ssp[64];        //   256 B  (total 46560 < 49152)

    const int bid = blockIdx.x;
    const int b   = bid / 20;
    const int pt  = bid % 20;
    const int oy  = pt >> 1;
    const int oxb = (pt & 1) * 5;
    const int tid = threadIdx.x;
    const int w    = tid >> 5;
    const int lane = tid & 31;

    for (int i = tid; i < 6272; i += 256) {
        int n = i >> 5, c = i & 31;
        smu[n * 36 + c] = mu_in[(size_t)(b * 196 + n) * 32 + c];
    }
    for (int i = tid; i < 2240; i += 256) {
        int r = i / 448, rem = i - r * 448;
        int x = rem >> 5, c = rem & 31;
        int n = (oy + r) * 14 + x;
        sds[i] = Sigma_in[(((size_t)b * 196 + n) * 196 + n) * 32 + c];
    }
    if (tid < 64) ssp[tid] = log1pf(expf(w_sigma[tid]));
    __syncthreads();

    if (w < 4) {
        // ---------------- GRAM (packed-c FFMA2) ----------------
        const int qh  = w & 1;
        const int kg  = w >> 1;
        const int kk0 = kg ? 13 : 0;
        const int kk1 = kg ? 25 : 13;
        int q[2], nq[2];
        #pragma unroll
        for (int j = 0; j < 2; j++) {
            q[j] = qh * 64 + j * 32 + lane;
            int qc = (q[j] < 100) ? q[j] : 0;
            nq[j] = (qc / 10) * 14 + qc % 10;
        }
        u64 gacc2[2][5];
        #pragma unroll
        for (int j = 0; j < 2; j++)
            #pragma unroll
            for (int pl = 0; pl < 5; pl++) gacc2[j][pl] = 0ull;

        const int prow0 = oy * 14 + oxb;
        #pragma unroll 1
        for (int kk = kk0; kk < kk1; kk++) {
            const int off = (kk / 5) * 14 + (kk % 5);
            const ulonglong2* b0 = (const ulonglong2*)(smu + (nq[0] + off) * 36);
            const ulonglong2* b1 = (const ulonglong2*)(smu + (nq[1] + off) * 36);
            const float* ar = smu + (prow0 + off) * 36;
            #pragma unroll
            for (int c4 = 0; c4 < 8; c4++) {
                ulonglong2 q0 = b0[c4];
                ulonglong2 q1 = b1[c4];
                #pragma unroll
                for (int pl = 0; pl < 5; pl++) {
                    ulonglong2 av = *(const ulonglong2*)(ar + pl * 36 + c4 * 4); // broadcast
                    ffma2(gacc2[0][pl], av.x, q0.x);
                    ffma2(gacc2[0][pl], av.y, q0.y);
                    ffma2(gacc2[1][pl], av.x, q1.x);
                    ffma2(gacc2[1][pl], av.y, q1.y);
                }
            }
        }
        #pragma unroll
        for (int j = 0; j < 2; j++) {
            if (q[j] < 100) {
                #pragma unroll
                for (int pl = 0; pl < 5; pl++)
                    sGp[kg][pl * 100 + q[j]] = unpack_sum(gacc2[j][pl]);
            }
        }
    } else if (w < 6) {
        // ---------------- CONV (packed-c FFMA2) ----------------
        const int kg  = w - 4;
        const int kk0 = kg ? 13 : 0;
        const int kk1 = kg ? 25 : 13;
        const float* wk = w_mu + lane;
        u64 acc2[10];
        #pragma unroll
        for (int j = 0; j < 10; j++) acc2[j] = 0ull;

        #pragma unroll 1
        for (int kk = kk0; kk < kk1; kk++) {
            const int off = (kk / 5) * 14 + (kk % 5);
            const float* mrow = smu + (oy * 14 + oxb + off) * 36;
            #pragma unroll
            for (int c4 = 0; c4 < 8; c4++) {
                const int m = kk * 32 + c4 * 4;
                float wa0 = wk[(m + 0) * 64], wb0 = wk[(m + 0) * 64 + 32];
                float wa1 = wk[(m + 1) * 64], wb1 = wk[(m + 1) * 64 + 32];
                float wa2 = wk[(m + 2) * 64], wb2 = wk[(m + 2) * 64 + 32];
                float wa3 = wk[(m + 3) * 64], wb3 = wk[(m + 3) * 64 + 32];
                u64 wA01 = pack2(wa0, wa1), wA23 = pack2(wa2, wa3);
                u64 wB01 = pack2(wb0, wb1), wB23 = pack2(wb2, wb3);
                #pragma unroll
                for (int j = 0; j < 5; j++) {
                    ulonglong2 mv = *(const ulonglong2*)(mrow + j * 36 + c4 * 4);
                    ffma2(acc2[j],     mv.x, wA01);
                    ffma2(acc2[j],     mv.y, wA23);
                    ffma2(acc2[5 + j], mv.x, wB01);
                    ffma2(acc2[5 + j], mv.y, wB23);
                }
            }
        }
        #pragma unroll
        for (int j = 0; j < 5; j++) {
            pcv[kg][j * 64 + lane]      = unpack_sum(acc2[j]);
            pcv[kg][j * 64 + 32 + lane] = unpack_sum(acc2[5 + j]);
        }
    } else {
        // ---------------- DIAG (packed-c FFMA2) ----------------
        const int kg  = w - 6;
        const int kk0 = kg ? 13 : 0;
        const int kk1 = kg ? 25 : 13;
        const float* wk = w_mu + lane;
        const u64 sp2a = pack2(ssp[lane], ssp[lane]);
        const u64 sp2b = pack2(ssp[lane + 32], ssp[lane + 32]);
        u64 acc2[10];
        #pragma unroll
        for (int j = 0; j < 10; j++) acc2[j] = 0ull;

        #pragma unroll 1
        for (int kk = kk0; kk < kk1; kk++) {
            const float* drow = sds + ((kk / 5) * 14 + (kk % 5) + oxb) * 32;
            #pragma unroll
            for (int c4 = 0; c4 < 8; c4++) {
                const int m = kk * 32 + c4 * 4;
                float wa0 = wk[(m + 0) * 64], wb0 = wk[(m + 0) * 64 + 32];
                float wa1 = wk[(m + 1) * 64], wb1 = wk[(m + 1) * 64 + 32];
                float wa2 = wk[(m + 2) * 64], wb2 = wk[(m + 2) * 64 + 32];
                float wa3 = wk[(m + 3) * 64], wb3 = wk[(m + 3) * 64 + 32];
                u64 wA01 = pack2(wa0, wa1), wA23 = pack2(wa2, wa3);
                u64 wB01 = pack2(wb0, wb1), wB23 = pack2(wb2, wb3);
                u64 eA01 = sp2a; ffma2(eA01, wA01, wA01);
                u64 eA23 = sp2a; ffma2(eA23, wA23, wA23);
                u64 eB01 = sp2b; ffma2(eB01, wB01, wB01);
                u64 eB23 = sp2b; ffma2(eB23, wB23, wB23);
                #pragma unroll
                for (int j = 0; j < 5; j++) {
                    ulonglong2 dv = *(const ulonglong2*)(drow + j * 32 + c4 * 4);
                    ffma2(acc2[j],     dv.x, eA01);
                    ffma2(acc2[j],     dv.y, eA23);
                    ffma2(acc2[5 + j], dv.x, eB01);
                    ffma2(acc2[5 + j], dv.y, eB23);
                }
            }
        }
        #pragma unroll
        for (int j = 0; j < 5; j++) {
            pdi[kg][j * 64 + lane]      = unpack_sum(acc2[j]);
            pdi[kg][j * 64 + 32 + lane] = unpack_sum(acc2[5 + j]);
        }
    }
    __syncthreads();

    // merge Gram kk-halves; write mu_out
    for (int i = tid; i < 500; i += 256)
        sGp[0][i] += sGp[1][i];
    if (mu_out != nullptr) {
        for (int i = tid; i < 320; i += 256) {
            int pl = i >> 6, k = i & 63;
            mu_out[(b * 100 + pt * 5 + pl) * 64 + k] = pcv[0][i] + pcv[1][i];
        }
    }
    __syncthreads();

    if (sigma_out == nullptr) return;

    // patch diagonal entries (q == p): add diag_vals, then abs where q==k
    for (int i = tid; i < 320; i += 256) {
        int pl = i >> 6, k = i & 63;
        int pg = pt * 5 + pl;
        float val = ssp[k] * sGp[0][pl * 100 + pg] + pdi[0][i] + pdi[1][i];
        if (pg == k) val = fabsf(val);
        sigma_out[(((size_t)(b * 100 + pg)) * 100 + pg) * 64 + k] = val;
    }

    // writer: all (p in strip, q != p, k): sp[k]*G, abs at q==k
    // kq = tid & 15 is invariant under +=256 -> hoist s4, k0.
    {
        const float4* sp4 = (const float4*)ssp;
        float4* out4 = (float4*)sigma_out;
        const int kq = tid & 15;
        const float4 s4 = sp4[kq];
        const int k0 = kq * 4;
        for (int t = tid >> 4; t < 500; t += 16) {
            const int pl = t / 100, ql = t - pl * 100;
            const int pg = pt * 5 + pl;
            if (ql == pg) continue;             // diagonal handled by patch
            const float g = sGp[0][pl * 100 + ql];
            float4 v;
            v.x = s4.x * g; v.y = s4.y * g; v.z = s4.z * g; v.w = s4.w * g;
            if      (ql == k0    ) v.x = fabsf(v.x);
            else if (ql == k0 + 1) v.y = fabsf(v.y);
            else if (ql == k0 + 2) v.z = fabsf(v.z);
            else if (ql == k0 + 3) v.w = fabsf(v.w);
            out4[((size_t)(b * 100 + pg) * 100 + ql) * 16 + kq] = v;
        }
    }
}

extern "C" void kernel_launch(void* const* d_in, const int* in_sizes, int n_in,
                              void* d_out, int out_size)
{
    const float* mu_in    = (const float*)d_in[0];
    const float* Sigma_in = (const float*)d_in[1];
    const float* w_mu     = (const float*)d_in[2];
    const float* w_sigma  = (const float*)d_in[3];
    for (int i = 0; i < n_in && i < 8; i++) {
        switch (in_sizes[i]) {
            case 32*14*14*32:  mu_in    = (const float*)d_in[i]; break;
            case 39337984:     Sigma_in = (const float*)d_in[i]; break;
            case 5*5*32*64:    w_mu     = (const float*)d_in[i]; break;
            case 64:           w_sigma  = (const float*)d_in[i]; break;
            default: break;
        }
    }

    float* out = (float*)d_out;
    float* mu_ptr  = nullptr;
    float* sig_ptr = nullptr;
    if (out_size == MU_ELEMS + SG_ELEMS) { mu_ptr = out; sig_ptr = out + MU_ELEMS; }
    else if (out_size == SG_ELEMS)       { sig_ptr = out; }
    else if (out_size == MU_ELEMS)       { mu_ptr = out; }
    else                                 { mu_ptr = out; sig_ptr = out + MU_ELEMS; }

    fused_kernel<<<640, 256>>>(mu_in, Sigma_in, w_mu, w_sigma, mu_ptr, sig_ptr);
}